// round 16
// baseline (speedup 1.0000x reference)
#include <cuda_runtime.h>
#include <cuda_fp16.h>
#include <math.h>
#include <stdint.h>

#define NTOK 8192
#define NEXP 8
#define IDIM 2816
#define HDIM 1024
#define NROWS (2*NTOK)                 // 16384 routed rows
#define BM 128                         // block M
#define BK 64                          // halfs of K per smem stage
#define STRH 72                        // smem row stride in halfs (144B)
#define STA (BM * STRH * 2)            // 18432 B per 128-row stage
#define STB128 (128 * STRH * 2)        // 18432 B per 128-row B stage
#define NSTAGE 3
#define MAX_TILES (NROWS/BM + NEXP)    // 136

// ---- device scratch ----
__device__ __half g_h[(size_t)NROWS * IDIM];            // 92 MB intermediate h (fp16)
__device__ __half g_part[(size_t)NROWS * HDIM];         // 33.5 MB fp16 GEMM2 partials
__device__ __half g_xh[(size_t)NTOK * HDIM];            // 16 MB X in fp16
__device__ __half g_w1h[(size_t)NEXP * IDIM * HDIM];    // 46 MB
__device__ __half g_w3h[(size_t)NEXP * IDIM * HDIM];    // 46 MB
__device__ __half g_w2h[(size_t)NEXP * HDIM * IDIM];    // 46 MB (filled inside k_gemm1)
__device__ int   g_bin_tok[NROWS];
__device__ int   g_tok_e[NTOK][2];
__device__ float g_tok_w[NTOK][2];
__device__ int   g_pos[NTOK][2];
__device__ int   g_tile_e[MAX_TILES];
__device__ int   g_tile_row0[MAX_TILES];
__device__ int   g_tile_m[MAX_TILES];
__device__ int   g_ntiles;

// ---------------- helpers ----------------
__device__ __forceinline__ void mma_f16(float* c, const uint32_t* a, const uint32_t* b) {
    asm volatile(
        "mma.sync.aligned.m16n8k16.row.col.f32.f16.f16.f32 "
        "{%0,%1,%2,%3},{%4,%5,%6,%7},{%8,%9},{%0,%1,%2,%3};"
        : "+f"(c[0]), "+f"(c[1]), "+f"(c[2]), "+f"(c[3])
        : "r"(a[0]), "r"(a[1]), "r"(a[2]), "r"(a[3]), "r"(b[0]), "r"(b[1]));
}
__device__ __forceinline__ void ldsm4(uint32_t* r, uint32_t addr) {
    asm volatile("ldmatrix.sync.aligned.m8n8.x4.shared.b16 {%0,%1,%2,%3}, [%4];"
        : "=r"(r[0]), "=r"(r[1]), "=r"(r[2]), "=r"(r[3]) : "r"(addr));
}
__device__ __forceinline__ uint32_t smem_u32(const void* p) {
    uint32_t a;
    asm("{ .reg .u64 t; cvta.to.shared.u64 t, %1; cvt.u32.u64 %0, t; }" : "=r"(a) : "l"(p));
    return a;
}
__device__ __forceinline__ void cpa16(uint32_t dst, const void* src) {
    asm volatile("cp.async.cg.shared.global [%0], [%1], 16;" :: "r"(dst), "l"(src));
}
__device__ __forceinline__ void cpa_commit() {
    asm volatile("cp.async.commit_group;" ::: "memory");
}
__device__ __forceinline__ void cpa_wait1() {
    asm volatile("cp.async.wait_group 1;" ::: "memory");
}

// ---------------- small kernels ----------------
// fused: router (blocks 0..31) + fp32->fp16 convert of X, W1, W3
__global__ void k_cvt_router(const float* __restrict__ X,  const float* __restrict__ RL,
                             const float* __restrict__ W1, const float* __restrict__ W3) {
    int tid = threadIdx.x;
    if (blockIdx.x < NTOK / 256) {
        int t = blockIdx.x * 256 + tid;
        float best = -INFINITY, second = -INFINITY;
        int b0 = 0, b1 = 0;
#pragma unroll
        for (int e = 0; e < NEXP; e++) {
            float v = RL[t * NEXP + e];
            if (v > best)        { second = best; b1 = b0; best = v; b0 = e; }
            else if (v > second) { second = v; b1 = e; }
        }
        float w0 = 1.0f / (1.0f + expf(second - best));
        g_tok_e[t][0] = b0;  g_tok_e[t][1] = b1;
        g_tok_w[t][0] = w0;  g_tok_w[t][1] = 1.0f - w0;
    }
    const int nX4 = NTOK * HDIM / 4;
    const int nW4 = NEXP * IDIM * HDIM / 4;
    const int total = nX4 + 2 * nW4;
    int stride = gridDim.x * blockDim.x;
    for (int i = blockIdx.x * blockDim.x + tid; i < total; i += stride) {
        const float4* src;
        uint2* dst;
        int j;
        if (i < nX4)                { src = (const float4*)X;  dst = (uint2*)g_xh;  j = i; }
        else if (i < nX4 + nW4)     { src = (const float4*)W1; dst = (uint2*)g_w1h; j = i - nX4; }
        else                        { src = (const float4*)W3; dst = (uint2*)g_w3h; j = i - nX4 - nW4; }
        float4 v = src[j];
        __half2 lo = __floats2half2_rn(v.x, v.y);
        __half2 hi = __floats2half2_rn(v.z, v.w);
        uint2 u; u.x = *(uint32_t*)&lo; u.y = *(uint32_t*)&hi;
        dst[j] = u;
    }
}

__global__ void k_prep_scatter() {
    __shared__ int hc[NEXP];
    __shared__ int cur[NEXP];
    int tid = threadIdx.x;
    if (tid < NEXP) hc[tid] = 0;
    __syncthreads();
    for (int t = tid; t < NTOK; t += 256) {
        atomicAdd(&hc[g_tok_e[t][0]], 1);
        atomicAdd(&hc[g_tok_e[t][1]], 1);
    }
    __syncthreads();
    if (tid == 0) {
        int off = 0, nt = 0;
        for (int e = 0; e < NEXP; e++) {
            int c = hc[e];
            cur[e] = off;
            for (int r = 0; r < c; r += BM) {
                g_tile_e[nt]    = e;
                g_tile_row0[nt] = off + r;
                g_tile_m[nt]    = min(BM, c - r);
                nt++;
            }
            off += c;
        }
        g_ntiles = nt;
    }
    __syncthreads();
    for (int t = tid; t < NTOK; t += 256) {
#pragma unroll
        for (int k = 0; k < 2; k++) {
            int e = g_tok_e[t][k];
            int p = atomicAdd(&cur[e], 1);
            g_bin_tok[p] = t;
            g_pos[t][k]  = p;
        }
    }
}

__global__ void k_gather(float* __restrict__ out) {
    const int n4 = NTOK * HDIM / 4;
    int stride = gridDim.x * blockDim.x;
    for (int i = blockIdx.x * blockDim.x + threadIdx.x; i < n4; i += stride) {
        int t = i >> 8;
        int c = i & 255;
        int p0 = g_pos[t][0], p1 = g_pos[t][1];
        float w0 = g_tok_w[t][0], w1 = g_tok_w[t][1];
        uint2 ua = ((const uint2*)g_part)[(size_t)p0 * 256 + c];
        uint2 ub = ((const uint2*)g_part)[(size_t)p1 * 256 + c];
        float2 aLo = __half22float2(*(__half2*)&ua.x);
        float2 aHi = __half22float2(*(__half2*)&ua.y);
        float2 bLo = __half22float2(*(__half2*)&ub.x);
        float2 bHi = __half22float2(*(__half2*)&ub.y);
        float4 o;
        o.x = w0 * aLo.x + w1 * bLo.x;
        o.y = w0 * aLo.y + w1 * bLo.y;
        o.z = w0 * aHi.x + w1 * bHi.x;
        o.w = w0 * aHi.y + w1 * bHi.y;
        ((float4*)out)[i] = o;
    }
}

// =====================================================================
// GEMM1 (interleaved B): h = silu(X@W1^T) * (X@W3^T)  [+ fused W2 convert]
// 256 threads (8 warps, 2Mx4N of 64x32 warp tiles), block tile 128(M) x 128(B rows),
// where B rows are 8-row blocks alternating W1/W3 for the same I columns:
//   smem B row R: block=R/8, pair=block/2, src=(block&1)? W3:W1, row nb+pair*8+(R%8)
// => each warp's n8 accumulator pair (nt=2q, 2q+1) holds (C1, C3) for the SAME
//    I columns in the SAME thread's registers: silu-mul fuses with no exchange.
// BK=64, 3-stage cp.async, fp32 accum, 2 CTAs/SM. 64 I-columns per CTA.
// smem: s_tok[1024] | A[3][18432] | B[3][18432] = 111616 B
// =====================================================================
#define G1_OFF_A   1024
#define G1_OFF_B   (G1_OFF_A + NSTAGE*STA)     // 56320
#define G1_SMEM    (G1_OFF_B + NSTAGE*STB128)  // 111616

__global__ void __launch_bounds__(256, 2)
k_gemm1(const float* __restrict__ W2) {
    int tid = threadIdx.x;

    // ---- fused W2 conversion (overlapped DRAM work; all CTAs participate)
    {
        const int nW4 = NEXP * IDIM * HDIM / 4;
        int ncta = gridDim.x * gridDim.y;
        int cta  = blockIdx.y * gridDim.x + blockIdx.x;
        int step = ncta * 256;
        for (int i = cta * 256 + tid; i < nW4; i += step) {
            float4 v = ((const float4*)W2)[i];
            __half2 lo = __floats2half2_rn(v.x, v.y);
            __half2 hi = __floats2half2_rn(v.z, v.w);
            uint2 u; u.x = *(uint32_t*)&lo; u.y = *(uint32_t*)&hi;
            ((uint2*)g_w2h)[i] = u;
        }
    }

    if ((int)blockIdx.y >= g_ntiles) return;
    int te   = g_tile_e[blockIdx.y];
    int row0 = g_tile_row0[blockIdx.y];
    int mcnt = g_tile_m[blockIdx.y];
    int nb   = blockIdx.x * 64;          // 64 I-columns per CTA

    extern __shared__ __align__(16) char smem[];
    int* s_tok = (int*)smem;
    uint32_t sbase = smem_u32(smem);

    if (tid < BM) s_tok[tid] = (tid < mcnt) ? g_bin_tok[row0 + tid] : 0;
    __syncthreads();

    const __half* W1e = g_w1h + (size_t)te * IDIM * HDIM;
    const __half* W3e = g_w3h + (size_t)te * IDIM * HDIM;

    // loaders: c = 16B chunk (0..7), r = row base (0..31); rows r+32j
    int c = tid & 7, r = tid >> 3;
    const __half* ag[4];
    const __half* bg[4];
#pragma unroll
    for (int j = 0; j < 4; j++) {
        int rr = r + 32 * j;
        ag[j] = g_xh + (size_t)s_tok[rr] * HDIM + c * 8;
        // interleaved B mapping
        int blk = rr >> 3, within = rr & 7;
        int pair = blk >> 1;
        const __half* Wsrc = (blk & 1) ? W3e : W1e;
        bg[j] = Wsrc + (size_t)(nb + pair * 8 + within) * HDIM + c * 8;
    }
    uint32_t so = (uint32_t)(r * 144 + c * 16);
    const uint32_t RS32 = 32 * 144;

    // warp/lane mapping: 8 warps, 2(M) x 4(N), warp tile 64x32 (of B rows)
    int warpId = tid >> 5, lane = tid & 31;
    int wm = (warpId & 1) * 64;
    int wn = (warpId >> 1) * 32;         // B-row offset; I columns = nb + wn/2 ..
    int fr = lane >> 2, fc = lane & 3;

    uint32_t a_lo = (uint32_t)((wm + (lane & 15)) * 144 + (lane >> 4) * 16);
    uint32_t b_lo = (uint32_t)((wn + (lane & 7) + ((lane >> 4) & 1) * 8) * 144 + ((lane >> 3) & 1) * 16);

    float acc[4][4][4];
#pragma unroll
    for (int i = 0; i < 4; i++)
#pragma unroll
        for (int j = 0; j < 4; j++)
#pragma unroll
            for (int k = 0; k < 4; k++) acc[i][j][k] = 0.f;

    const int NIT = HDIM / BK;   // 16

#pragma unroll
    for (int s = 0; s < NSTAGE - 1; s++) {
        int kt = s * BK;
        uint32_t sa = sbase + G1_OFF_A + s * STA + so;
        uint32_t sb = sbase + G1_OFF_B + s * STB128 + so;
#pragma unroll
        for (int j = 0; j < 4; j++) {
            cpa16(sa + j * RS32, ag[j] + kt);
            cpa16(sb + j * RS32, bg[j] + kt);
        }
        cpa_commit();
    }

    for (int it = 0; it < NIT; it++) {
        cpa_wait1();
        __syncthreads();
        if (it + NSTAGE - 1 < NIT) {
            int s = (it + NSTAGE - 1) % NSTAGE;
            int kt = (it + NSTAGE - 1) * BK;
            uint32_t sa = sbase + G1_OFF_A + s * STA + so;
            uint32_t sb = sbase + G1_OFF_B + s * STB128 + so;
#pragma unroll
            for (int j = 0; j < 4; j++) {
                cpa16(sa + j * RS32, ag[j] + kt);
                cpa16(sb + j * RS32, bg[j] + kt);
            }
        }
        cpa_commit();

        int st = it % NSTAGE;
        uint32_t abase = sbase + G1_OFF_A + st * STA + a_lo;
        uint32_t bbase = sbase + G1_OFF_B + st * STB128 + b_lo;
#pragma unroll
        for (int kk = 0; kk < BK; kk += 16) {
            uint32_t a[4][4];
#pragma unroll
            for (int mt = 0; mt < 4; mt++)
                ldsm4(a[mt], abase + mt * 16 * 144 + kk * 2);
            uint32_t bf[2][4];
#pragma unroll
            for (int p = 0; p < 2; p++)
                ldsm4(bf[p], bbase + p * 16 * 144 + kk * 2);
#pragma unroll
            for (int p = 0; p < 2; p++)
#pragma unroll
                for (int mt = 0; mt < 4; mt++) {
                    mma_f16(acc[mt][2*p],   a[mt], &bf[p][0]);  // W1 n8 tile
                    mma_f16(acc[mt][2*p+1], a[mt], &bf[p][2]);  // W3 n8 tile
                }
        }
    }

    // ---- fused epilogue: acc[mt][2q] = C1, acc[mt][2q+1] = C3 for the SAME
    //      I columns (nb + wn/2 + q*8 + fc*2). h = silu(c1) * c3 -> g_h (fp16).
#pragma unroll
    for (int mt = 0; mt < 4; mt++) {
        int m_lo = wm + mt * 16 + fr;
        int m_hi = m_lo + 8;
#pragma unroll
        for (int q = 0; q < 2; q++) {
            int col = nb + (wn >> 1) + q * 8 + fc * 2;
            float* c1 = acc[mt][2*q];
            float* c3 = acc[mt][2*q+1];
            if (m_lo < mcnt) {
                float h0 = c1[0] / (1.0f + expf(-c1[0])) * c3[0];
                float h1 = c1[1] / (1.0f + expf(-c1[1])) * c3[1];
                *(__half2*)&g_h[(size_t)(row0 + m_lo) * IDIM + col] = __floats2half2_rn(h0, h1);
            }
            if (m_hi < mcnt) {
                float h2 = c1[2] / (1.0f + expf(-c1[2])) * c3[2];
                float h3 = c1[3] / (1.0f + expf(-c1[3])) * c3[3];
                *(__half2*)&g_h[(size_t)(row0 + m_hi) * IDIM + col] = __floats2half2_rn(h2, h3);
            }
        }
    }
}

// =====================================================================
// GEMM2 (unchanged champion): part = h @ W2^T   (fp16 partials)
// 256 threads (8 warps, 2Mx4N of 64x32 warp tiles), block tile 128x128,
// BK=64, 3-stage, fp32 accum, 2 CTAs/SM.
// smem: 1024 | A[3][18432] | B[3][18432] = 111616 B
// =====================================================================
#define G2_OFF_A  1024
#define G2_OFF_B  (G2_OFF_A + NSTAGE*STA)      // 56320
#define G2_SMEM   (G2_OFF_B + NSTAGE*STB128)   // 111616

__global__ void __launch_bounds__(256, 2)
k_gemm2() {
    if ((int)blockIdx.y >= g_ntiles) return;
    int te   = g_tile_e[blockIdx.y];
    int row0 = g_tile_row0[blockIdx.y];
    int mcnt = g_tile_m[blockIdx.y];
    int nb   = blockIdx.x * 128;

    extern __shared__ __align__(16) char smem[];
    uint32_t sbase = smem_u32(smem);
    int tid = threadIdx.x;

    const __half* W2e = g_w2h + (size_t)te * HDIM * IDIM;

    int c = tid & 7, r = tid >> 3;
    const __half* ag[4];
    const __half* bg[4];
#pragma unroll
    for (int j = 0; j < 4; j++) {
        int rr = r + 32 * j;
        ag[j] = g_h + (size_t)(row0 + (rr < mcnt ? rr : 0)) * IDIM + c * 8;
        bg[j] = W2e + (size_t)(nb + rr) * IDIM + c * 8;
    }
    uint32_t so = (uint32_t)(r * 144 + c * 16);
    const uint32_t RS32 = 32 * 144;

    int warpId = tid >> 5, lane = tid & 31;
    int wm = (warpId & 1) * 64;
    int wn = (warpId >> 1) * 32;
    int fr = lane >> 2, fc = lane & 3;

    uint32_t a_lo = (uint32_t)((wm + (lane & 15)) * 144 + (lane >> 4) * 16);
    uint32_t b_lo = (uint32_t)((wn + (lane & 7) + ((lane >> 4) & 1) * 8) * 144 + ((lane >> 3) & 1) * 16);

    float acc[4][4][4];
#pragma unroll
    for (int i = 0; i < 4; i++)
#pragma unroll
        for (int j = 0; j < 4; j++)
#pragma unroll
            for (int k = 0; k < 4; k++) acc[i][j][k] = 0.f;

    const int NIT = IDIM / BK;   // 44

#pragma unroll
    for (int s = 0; s < NSTAGE - 1; s++) {
        int kt = s * BK;
        uint32_t sa = sbase + G2_OFF_A + s * STA + so;
        uint32_t sb = sbase + G2_OFF_B + s * STB128 + so;
#pragma unroll
        for (int j = 0; j < 4; j++) {
            cpa16(sa + j * RS32, ag[j] + kt);
            cpa16(sb + j * RS32, bg[j] + kt);
        }
        cpa_commit();
    }

    for (int it = 0; it < NIT; it++) {
        cpa_wait1();
        __syncthreads();
        if (it + NSTAGE - 1 < NIT) {
            int s = (it + NSTAGE - 1) % NSTAGE;
            int kt = (it + NSTAGE - 1) * BK;
            uint32_t sa = sbase + G2_OFF_A + s * STA + so;
            uint32_t sb = sbase + G2_OFF_B + s * STB128 + so;
#pragma unroll
            for (int j = 0; j < 4; j++) {
                cpa16(sa + j * RS32, ag[j] + kt);
                cpa16(sb + j * RS32, bg[j] + kt);
            }
        }
        cpa_commit();

        int st = it % NSTAGE;
        uint32_t abase = sbase + G2_OFF_A + st * STA + a_lo;
        uint32_t bbase = sbase + G2_OFF_B + st * STB128 + b_lo;
#pragma unroll
        for (int kk = 0; kk < BK; kk += 16) {
            uint32_t a[4][4];
#pragma unroll
            for (int mt = 0; mt < 4; mt++)
                ldsm4(a[mt], abase + mt * 16 * 144 + kk * 2);
            uint32_t bf[2][4];
#pragma unroll
            for (int p = 0; p < 2; p++)
                ldsm4(bf[p], bbase + p * 16 * 144 + kk * 2);
#pragma unroll
            for (int p = 0; p < 2; p++)
#pragma unroll
                for (int mt = 0; mt < 4; mt++) {
                    mma_f16(acc[mt][2*p],   a[mt], &bf[p][0]);
                    mma_f16(acc[mt][2*p+1], a[mt], &bf[p][2]);
                }
        }
    }

    // epilogue: fp16 partial stores to contiguous bin rows
#pragma unroll
    for (int mt = 0; mt < 4; mt++) {
        int m_lo = wm + mt * 16 + fr;
        int m_hi = m_lo + 8;
#pragma unroll
        for (int nt = 0; nt < 4; nt++) {
            int col = nb + wn + nt * 8 + fc * 2;
            if (m_lo < mcnt) {
                __half2 v = __floats2half2_rn(acc[mt][nt][0], acc[mt][nt][1]);
                *(__half2*)&g_part[(size_t)(row0 + m_lo) * HDIM + col] = v;
            }
            if (m_hi < mcnt) {
                __half2 v = __floats2half2_rn(acc[mt][nt][2], acc[mt][nt][3]);
                *(__half2*)&g_part[(size_t)(row0 + m_hi) * HDIM + col] = v;
            }
        }
    }
}

// ---------------- launch ----------------
extern "C" void kernel_launch(void* const* d_in, const int* in_sizes, int n_in,
                              void* d_out, int out_size) {
    const float* X  = (const float*)d_in[0];  // [T,H]
    const float* RL = (const float*)d_in[1];  // [T,E]
    const float* W1 = (const float*)d_in[2];  // [E,I,H]
    const float* W3 = (const float*)d_in[3];  // [E,I,H]
    const float* W2 = (const float*)d_in[4];  // [E,H,I]
    float* out = (float*)d_out;               // [T,H]

    cudaFuncSetAttribute(k_gemm1, cudaFuncAttributeMaxDynamicSharedMemorySize, G1_SMEM);
    cudaFuncSetAttribute(k_gemm2, cudaFuncAttributeMaxDynamicSharedMemorySize, G2_SMEM);

    k_cvt_router<<<2048, 256>>>(X, RL, W1, W3);      // 1 (router fused in)
    k_prep_scatter<<<1, 256>>>();                    // 2

    dim3 g1(IDIM / 64, MAX_TILES);                   // 3: 44 x 136
    k_gemm1<<<g1, 256, G1_SMEM>>>(W2);               // also converts W2 -> g_w2h

    dim3 g2(HDIM / 128, MAX_TILES);                  // 4: 8 x 136  <- ncu capture slot
    k_gemm2<<<g2, 256, G2_SMEM>>>();

    k_gather<<<2048, 256>>>(out);                    // 5
}

// round 17
// speedup vs baseline: 1.0132x; 1.0132x over previous
#include <cuda_runtime.h>
#include <cuda_fp16.h>
#include <math.h>
#include <stdint.h>

#define NTOK 8192
#define NEXP 8
#define IDIM 2816
#define HDIM 1024
#define NROWS (2*NTOK)                 // 16384 routed rows
#define BM 128                         // block M
#define BN 64                          // gemm1 block N
#define BK 64                          // halfs of K per smem stage
#define STRH 72                        // smem row stride in halfs (144B)
#define STA (BM * STRH * 2)            // 18432 B per 128-row stage
#define STB (BN * STRH * 2)            // 9216 B per 64-row stage
#define NSTAGE 3
#define MAX_TILES (NROWS/BM + NEXP)    // 136

// ---- device scratch ----
__device__ __half g_h[(size_t)NROWS * IDIM];            // 92 MB intermediate h (fp16)
__device__ __half g_part[(size_t)NROWS * HDIM];         // 33.5 MB fp16 GEMM2 partials
__device__ __half g_xh[(size_t)NTOK * HDIM];            // 16 MB X in fp16
__device__ __half g_w1h[(size_t)NEXP * IDIM * HDIM];    // 46 MB
__device__ __half g_w3h[(size_t)NEXP * IDIM * HDIM];    // 46 MB
__device__ __half g_w2h[(size_t)NEXP * HDIM * IDIM];    // 46 MB (filled inside k_gemm1)
__device__ int   g_bin_tok[NROWS];
__device__ int   g_tok_e[NTOK][2];
__device__ float g_tok_w[NTOK][2];
__device__ int   g_pos[NTOK][2];
__device__ int   g_tile_e[MAX_TILES];
__device__ int   g_tile_row0[MAX_TILES];
__device__ int   g_tile_m[MAX_TILES];
__device__ int   g_ntiles;

// ---------------- helpers ----------------
__device__ __forceinline__ void mma_f16(float* c, const uint32_t* a, const uint32_t* b) {
    asm volatile(
        "mma.sync.aligned.m16n8k16.row.col.f32.f16.f16.f32 "
        "{%0,%1,%2,%3},{%4,%5,%6,%7},{%8,%9},{%0,%1,%2,%3};"
        : "+f"(c[0]), "+f"(c[1]), "+f"(c[2]), "+f"(c[3])
        : "r"(a[0]), "r"(a[1]), "r"(a[2]), "r"(a[3]), "r"(b[0]), "r"(b[1]));
}
__device__ __forceinline__ void ldsm4(uint32_t* r, uint32_t addr) {
    asm volatile("ldmatrix.sync.aligned.m8n8.x4.shared.b16 {%0,%1,%2,%3}, [%4];"
        : "=r"(r[0]), "=r"(r[1]), "=r"(r[2]), "=r"(r[3]) : "r"(addr));
}
__device__ __forceinline__ uint32_t smem_u32(const void* p) {
    uint32_t a;
    asm("{ .reg .u64 t; cvta.to.shared.u64 t, %1; cvt.u32.u64 %0, t; }" : "=r"(a) : "l"(p));
    return a;
}
__device__ __forceinline__ void cpa16(uint32_t dst, const void* src) {
    asm volatile("cp.async.cg.shared.global [%0], [%1], 16;" :: "r"(dst), "l"(src));
}
__device__ __forceinline__ void cpa_commit() {
    asm volatile("cp.async.commit_group;" ::: "memory");
}
__device__ __forceinline__ void cpa_wait1() {
    asm volatile("cp.async.wait_group 1;" ::: "memory");
}
__device__ __forceinline__ float silu(float x) {
    return x / (1.0f + __expf(-x));
}

// ---------------- small kernels ----------------
// fused: router (blocks 0..31) + fp32->fp16 convert of X, W1, W3
__global__ void k_cvt_router(const float* __restrict__ X,  const float* __restrict__ RL,
                             const float* __restrict__ W1, const float* __restrict__ W3) {
    int tid = threadIdx.x;
    if (blockIdx.x < NTOK / 256) {
        int t = blockIdx.x * 256 + tid;
        float best = -INFINITY, second = -INFINITY;
        int b0 = 0, b1 = 0;
#pragma unroll
        for (int e = 0; e < NEXP; e++) {
            float v = RL[t * NEXP + e];
            if (v > best)        { second = best; b1 = b0; best = v; b0 = e; }
            else if (v > second) { second = v; b1 = e; }
        }
        float w0 = 1.0f / (1.0f + __expf(second - best));
        g_tok_e[t][0] = b0;  g_tok_e[t][1] = b1;
        g_tok_w[t][0] = w0;  g_tok_w[t][1] = 1.0f - w0;
    }
    const int nX4 = NTOK * HDIM / 4;
    const int nW4 = NEXP * IDIM * HDIM / 4;
    const int total = nX4 + 2 * nW4;
    int stride = gridDim.x * blockDim.x;
    for (int i = blockIdx.x * blockDim.x + tid; i < total; i += stride) {
        const float4* src;
        uint2* dst;
        int j;
        if (i < nX4)                { src = (const float4*)X;  dst = (uint2*)g_xh;  j = i; }
        else if (i < nX4 + nW4)     { src = (const float4*)W1; dst = (uint2*)g_w1h; j = i - nX4; }
        else                        { src = (const float4*)W3; dst = (uint2*)g_w3h; j = i - nX4 - nW4; }
        float4 v = src[j];
        __half2 lo = __floats2half2_rn(v.x, v.y);
        __half2 hi = __floats2half2_rn(v.z, v.w);
        uint2 u; u.x = *(uint32_t*)&lo; u.y = *(uint32_t*)&hi;
        dst[j] = u;
    }
}

__global__ void k_prep_scatter() {
    __shared__ int hc[NEXP];
    __shared__ int cur[NEXP];
    int tid = threadIdx.x;
    if (tid < NEXP) hc[tid] = 0;
    __syncthreads();
    for (int t = tid; t < NTOK; t += 256) {
        atomicAdd(&hc[g_tok_e[t][0]], 1);
        atomicAdd(&hc[g_tok_e[t][1]], 1);
    }
    __syncthreads();
    if (tid == 0) {
        int off = 0, nt = 0;
        for (int e = 0; e < NEXP; e++) {
            int c = hc[e];
            cur[e] = off;
            for (int r = 0; r < c; r += BM) {
                g_tile_e[nt]    = e;
                g_tile_row0[nt] = off + r;
                g_tile_m[nt]    = min(BM, c - r);
                nt++;
            }
            off += c;
        }
        g_ntiles = nt;
    }
    __syncthreads();
    for (int t = tid; t < NTOK; t += 256) {
#pragma unroll
        for (int k = 0; k < 2; k++) {
            int e = g_tok_e[t][k];
            int p = atomicAdd(&cur[e], 1);
            g_bin_tok[p] = t;
            g_pos[t][k]  = p;
        }
    }
}

__global__ void k_gather(float* __restrict__ out) {
    const int n4 = NTOK * HDIM / 4;
    int stride = gridDim.x * blockDim.x;
    for (int i = blockIdx.x * blockDim.x + threadIdx.x; i < n4; i += stride) {
        int t = i >> 8;
        int c = i & 255;
        int p0 = g_pos[t][0], p1 = g_pos[t][1];
        float w0 = g_tok_w[t][0], w1 = g_tok_w[t][1];
        uint2 ua = ((const uint2*)g_part)[(size_t)p0 * 256 + c];
        uint2 ub = ((const uint2*)g_part)[(size_t)p1 * 256 + c];
        float2 aLo = __half22float2(*(__half2*)&ua.x);
        float2 aHi = __half22float2(*(__half2*)&ua.y);
        float2 bLo = __half22float2(*(__half2*)&ub.x);
        float2 bHi = __half22float2(*(__half2*)&ub.y);
        float4 o;
        o.x = w0 * aLo.x + w1 * bLo.x;
        o.y = w0 * aLo.y + w1 * bLo.y;
        o.z = w0 * aHi.x + w1 * bHi.x;
        o.w = w0 * aHi.y + w1 * bHi.y;
        ((float4*)out)[i] = o;
    }
}

// =====================================================================
// GEMM1 (champion): h = silu(X@W1^T) * (X@W3^T)  [+ W2 convert in TAIL]
// 256 threads (8 warps, 4Mx2N of 32x32 warp tiles), block tile 128x64,
// BK=64 halfs, 3-stage cp.async (wait_group 1), fp32 accum, 2 CTAs/SM.
// smem: s_tok[1024] | A[3][18432] | B1[3][9216] | B3[3][9216] = 111616 B
// =====================================================================
#define G1_OFF_A   1024
#define G1_OFF_B1  (G1_OFF_A  + NSTAGE*STA)    // 56320
#define G1_OFF_B3  (G1_OFF_B1 + NSTAGE*STB)    // 83968
#define G1_SMEM    (G1_OFF_B3 + NSTAGE*STB)    // 111616

__global__ void __launch_bounds__(256, 2)
k_gemm1(const float* __restrict__ W2) {
    int tid = threadIdx.x;
    bool active = ((int)blockIdx.y < g_ntiles);

    if (active) {
        int te   = g_tile_e[blockIdx.y];
        int row0 = g_tile_row0[blockIdx.y];
        int mcnt = g_tile_m[blockIdx.y];
        int nb   = blockIdx.x * BN;

        extern __shared__ __align__(16) char smem[];
        int* s_tok = (int*)smem;
        uint32_t sbase = smem_u32(smem);

        if (tid < BM) s_tok[tid] = (tid < mcnt) ? g_bin_tok[row0 + tid] : 0;
        __syncthreads();

        const __half* W1e = g_w1h + (size_t)te * IDIM * HDIM;
        const __half* W3e = g_w3h + (size_t)te * IDIM * HDIM;

        int c = tid & 7, r = tid >> 3;
        const __half* ag[4];
#pragma unroll
        for (int j = 0; j < 4; j++)
            ag[j] = g_xh + (size_t)s_tok[r + 32 * j] * HDIM + c * 8;
        const __half* b1g0 = W1e + (size_t)(nb + r) * HDIM + c * 8;
        const __half* b1g1 = W1e + (size_t)(nb + r + 32) * HDIM + c * 8;
        const __half* b3g0 = W3e + (size_t)(nb + r) * HDIM + c * 8;
        const __half* b3g1 = W3e + (size_t)(nb + r + 32) * HDIM + c * 8;
        uint32_t so = (uint32_t)(r * 144 + c * 16);
        const uint32_t RS32 = 32 * 144;

        int warpId = tid >> 5, lane = tid & 31;
        int wm = (warpId & 3) * 32;
        int wn = (warpId >> 2) * 32;
        int fr = lane >> 2, fc = lane & 3;

        uint32_t a_lo = (uint32_t)((wm + (lane & 15)) * 144 + (lane >> 4) * 16);
        uint32_t b_lo = (uint32_t)((wn + (lane & 7) + ((lane >> 4) & 1) * 8) * 144 + ((lane >> 3) & 1) * 16);

        float acc1[2][4][4], acc3[2][4][4];
#pragma unroll
        for (int i = 0; i < 2; i++)
#pragma unroll
            for (int j = 0; j < 4; j++)
#pragma unroll
                for (int k = 0; k < 4; k++) { acc1[i][j][k] = 0.f; acc3[i][j][k] = 0.f; }

        const int NIT = HDIM / BK;   // 16

#pragma unroll
        for (int s = 0; s < NSTAGE - 1; s++) {
            int kt = s * BK;
            uint32_t sa = sbase + G1_OFF_A  + s * STA + so;
            uint32_t s1 = sbase + G1_OFF_B1 + s * STB + so;
            uint32_t s3 = sbase + G1_OFF_B3 + s * STB + so;
#pragma unroll
            for (int j = 0; j < 4; j++) cpa16(sa + j * RS32, ag[j] + kt);
            cpa16(s1, b1g0 + kt);  cpa16(s1 + RS32, b1g1 + kt);
            cpa16(s3, b3g0 + kt);  cpa16(s3 + RS32, b3g1 + kt);
            cpa_commit();
        }

        for (int it = 0; it < NIT; it++) {
            cpa_wait1();
            __syncthreads();
            if (it + NSTAGE - 1 < NIT) {
                int s = (it + NSTAGE - 1) % NSTAGE;
                int kt = (it + NSTAGE - 1) * BK;
                uint32_t sa = sbase + G1_OFF_A  + s * STA + so;
                uint32_t s1 = sbase + G1_OFF_B1 + s * STB + so;
                uint32_t s3 = sbase + G1_OFF_B3 + s * STB + so;
#pragma unroll
                for (int j = 0; j < 4; j++) cpa16(sa + j * RS32, ag[j] + kt);
                cpa16(s1, b1g0 + kt);  cpa16(s1 + RS32, b1g1 + kt);
                cpa16(s3, b3g0 + kt);  cpa16(s3 + RS32, b3g1 + kt);
            }
            cpa_commit();

            int st = it % NSTAGE;
            uint32_t abase = sbase + G1_OFF_A  + st * STA + a_lo;
            uint32_t b1b   = sbase + G1_OFF_B1 + st * STB + b_lo;
            uint32_t b3b   = sbase + G1_OFF_B3 + st * STB + b_lo;
#pragma unroll
            for (int kk = 0; kk < BK; kk += 16) {
                uint32_t a[2][4];
#pragma unroll
                for (int mt = 0; mt < 2; mt++)
                    ldsm4(a[mt], abase + mt * 16 * 144 + kk * 2);
                uint32_t bf1[2][4], bf3[2][4];
#pragma unroll
                for (int p = 0; p < 2; p++) {
                    ldsm4(bf1[p], b1b + p * 16 * 144 + kk * 2);
                    ldsm4(bf3[p], b3b + p * 16 * 144 + kk * 2);
                }
#pragma unroll
                for (int p = 0; p < 2; p++)
#pragma unroll
                    for (int mt = 0; mt < 2; mt++) {
                        mma_f16(acc1[mt][2*p],   a[mt], &bf1[p][0]);
                        mma_f16(acc1[mt][2*p+1], a[mt], &bf1[p][2]);
                        mma_f16(acc3[mt][2*p],   a[mt], &bf3[p][0]);
                        mma_f16(acc3[mt][2*p+1], a[mt], &bf3[p][2]);
                    }
            }
        }

        // epilogue: h = silu(c1)*c3 -> g_h (fp16)
#pragma unroll
        for (int mt = 0; mt < 2; mt++) {
            int m_lo = wm + mt * 16 + fr;
            int m_hi = m_lo + 8;
#pragma unroll
            for (int nt = 0; nt < 4; nt++) {
                int col = nb + wn + nt * 8 + fc * 2;
                if (m_lo < mcnt) {
                    float h0 = silu(acc1[mt][nt][0]) * acc3[mt][nt][0];
                    float h1 = silu(acc1[mt][nt][1]) * acc3[mt][nt][1];
                    *(__half2*)&g_h[(size_t)(row0 + m_lo) * IDIM + col] = __floats2half2_rn(h0, h1);
                }
                if (m_hi < mcnt) {
                    float h2 = silu(acc1[mt][nt][2]) * acc3[mt][nt][2];
                    float h3 = silu(acc1[mt][nt][3]) * acc3[mt][nt][3];
                    *(__half2*)&g_h[(size_t)(row0 + m_hi) * IDIM + col] = __floats2half2_rn(h2, h3);
                }
            }
        }
    }

    // ---- W2 conversion in the TAIL (fills CTA drain instead of delaying
    //      the mainloop start; all CTAs incl. ghosts participate)
    {
        const int nW4 = NEXP * IDIM * HDIM / 4;
        int ncta = gridDim.x * gridDim.y;
        int cta  = blockIdx.y * gridDim.x + blockIdx.x;
        int step = ncta * 256;
        for (int i = cta * 256 + tid; i < nW4; i += step) {
            float4 v = ((const float4*)W2)[i];
            __half2 lo = __floats2half2_rn(v.x, v.y);
            __half2 hi = __floats2half2_rn(v.z, v.w);
            uint2 u; u.x = *(uint32_t*)&lo; u.y = *(uint32_t*)&hi;
            ((uint2*)g_w2h)[i] = u;
        }
    }
}

// =====================================================================
// GEMM2 (unchanged champion): part = h @ W2^T   (fp16 partials)
// 256 threads (8 warps, 2Mx4N of 64x32 warp tiles), block tile 128x128,
// BK=64, 3-stage, fp32 accum, 2 CTAs/SM.
// smem: 1024 | A[3][18432] | B[3][18432] = 111616 B
// =====================================================================
#define BN2 128
#define STB2 (BN2 * STRH * 2)                // 18432
#define G2_OFF_A  1024
#define G2_OFF_B  (G2_OFF_A + NSTAGE*STA)    // 56320
#define G2_SMEM   (G2_OFF_B + NSTAGE*STB2)   // 111616

__global__ void __launch_bounds__(256, 2)
k_gemm2() {
    if ((int)blockIdx.y >= g_ntiles) return;
    int te   = g_tile_e[blockIdx.y];
    int row0 = g_tile_row0[blockIdx.y];
    int mcnt = g_tile_m[blockIdx.y];
    int nb   = blockIdx.x * BN2;

    extern __shared__ __align__(16) char smem[];
    uint32_t sbase = smem_u32(smem);
    int tid = threadIdx.x;

    const __half* W2e = g_w2h + (size_t)te * HDIM * IDIM;

    int c = tid & 7, r = tid >> 3;
    const __half* ag[4];
    const __half* bg[4];
#pragma unroll
    for (int j = 0; j < 4; j++) {
        int rr = r + 32 * j;
        ag[j] = g_h + (size_t)(row0 + (rr < mcnt ? rr : 0)) * IDIM + c * 8;
        bg[j] = W2e + (size_t)(nb + rr) * IDIM + c * 8;
    }
    uint32_t so = (uint32_t)(r * 144 + c * 16);
    const uint32_t RS32 = 32 * 144;

    int warpId = tid >> 5, lane = tid & 31;
    int wm = (warpId & 1) * 64;
    int wn = (warpId >> 1) * 32;
    int fr = lane >> 2, fc = lane & 3;

    uint32_t a_lo = (uint32_t)((wm + (lane & 15)) * 144 + (lane >> 4) * 16);
    uint32_t b_lo = (uint32_t)((wn + (lane & 7) + ((lane >> 4) & 1) * 8) * 144 + ((lane >> 3) & 1) * 16);

    float acc[4][4][4];
#pragma unroll
    for (int i = 0; i < 4; i++)
#pragma unroll
        for (int j = 0; j < 4; j++)
#pragma unroll
            for (int k = 0; k < 4; k++) acc[i][j][k] = 0.f;

    const int NIT = IDIM / BK;   // 44

#pragma unroll
    for (int s = 0; s < NSTAGE - 1; s++) {
        int kt = s * BK;
        uint32_t sa = sbase + G2_OFF_A + s * STA + so;
        uint32_t sb = sbase + G2_OFF_B + s * STB2 + so;
#pragma unroll
        for (int j = 0; j < 4; j++) {
            cpa16(sa + j * RS32, ag[j] + kt);
            cpa16(sb + j * RS32, bg[j] + kt);
        }
        cpa_commit();
    }

    for (int it = 0; it < NIT; it++) {
        cpa_wait1();
        __syncthreads();
        if (it + NSTAGE - 1 < NIT) {
            int s = (it + NSTAGE - 1) % NSTAGE;
            int kt = (it + NSTAGE - 1) * BK;
            uint32_t sa = sbase + G2_OFF_A + s * STA + so;
            uint32_t sb = sbase + G2_OFF_B + s * STB2 + so;
#pragma unroll
            for (int j = 0; j < 4; j++) {
                cpa16(sa + j * RS32, ag[j] + kt);
                cpa16(sb + j * RS32, bg[j] + kt);
            }
        }
        cpa_commit();

        int st = it % NSTAGE;
        uint32_t abase = sbase + G2_OFF_A + st * STA + a_lo;
        uint32_t bbase = sbase + G2_OFF_B + st * STB2 + b_lo;
#pragma unroll
        for (int kk = 0; kk < BK; kk += 16) {
            uint32_t a[4][4];
#pragma unroll
            for (int mt = 0; mt < 4; mt++)
                ldsm4(a[mt], abase + mt * 16 * 144 + kk * 2);
            uint32_t bf[2][4];
#pragma unroll
            for (int p = 0; p < 2; p++)
                ldsm4(bf[p], bbase + p * 16 * 144 + kk * 2);
#pragma unroll
            for (int p = 0; p < 2; p++)
#pragma unroll
                for (int mt = 0; mt < 4; mt++) {
                    mma_f16(acc[mt][2*p],   a[mt], &bf[p][0]);
                    mma_f16(acc[mt][2*p+1], a[mt], &bf[p][2]);
                }
        }
    }

    // epilogue: fp16 partial stores to contiguous bin rows
#pragma unroll
    for (int mt = 0; mt < 4; mt++) {
        int m_lo = wm + mt * 16 + fr;
        int m_hi = m_lo + 8;
#pragma unroll
        for (int nt = 0; nt < 4; nt++) {
            int col = nb + wn + nt * 8 + fc * 2;
            if (m_lo < mcnt) {
                __half2 v = __floats2half2_rn(acc[mt][nt][0], acc[mt][nt][1]);
                *(__half2*)&g_part[(size_t)(row0 + m_lo) * HDIM + col] = v;
            }
            if (m_hi < mcnt) {
                __half2 v = __floats2half2_rn(acc[mt][nt][2], acc[mt][nt][3]);
                *(__half2*)&g_part[(size_t)(row0 + m_hi) * HDIM + col] = v;
            }
        }
    }
}

// ---------------- launch ----------------
extern "C" void kernel_launch(void* const* d_in, const int* in_sizes, int n_in,
                              void* d_out, int out_size) {
    const float* X  = (const float*)d_in[0];  // [T,H]
    const float* RL = (const float*)d_in[1];  // [T,E]
    const float* W1 = (const float*)d_in[2];  // [E,I,H]
    const float* W3 = (const float*)d_in[3];  // [E,I,H]
    const float* W2 = (const float*)d_in[4];  // [E,H,I]
    float* out = (float*)d_out;               // [T,H]

    cudaFuncSetAttribute(k_gemm1, cudaFuncAttributeMaxDynamicSharedMemorySize, G1_SMEM);
    cudaFuncSetAttribute(k_gemm2, cudaFuncAttributeMaxDynamicSharedMemorySize, G2_SMEM);

    k_cvt_router<<<2048, 256>>>(X, RL, W1, W3);      // 1 (router fused in)
    k_prep_scatter<<<1, 256>>>();                    // 2

    dim3 g1(IDIM / BN, MAX_TILES);                   // 3: 44 x 136
    k_gemm1<<<g1, 256, G1_SMEM>>>(W2);               // W2 -> g_w2h in kernel tail

    dim3 g2(HDIM / BN2, MAX_TILES);                  // 4: 8 x 136  <- ncu capture slot
    k_gemm2<<<g2, 256, G2_SMEM>>>();

    k_gather<<<2048, 256>>>(out);                    // 5
}